// round 6
// baseline (speedup 1.0000x reference)
#include <cuda_runtime.h>

// CFConv: y[i] = sum_{e: idx_i[e]==i} x[idx_j[e]] * Wij[e]
// x:[50000,64] f32, Wij:[E=1.25M,64] f32, idx_i sorted.
//
// R6: cp.async (LDGSTS) 8-deep SMEM ring per warp for BOTH the Wij stream and
// the x gather -> prefetch depth 8 with zero register staging. Half-warp
// float4 lanes, sorted-segment register accumulation, plain stores for
// interior segments, red.global.add.v4.f32 at task boundaries.

#define FEAT   64
#define F4     (FEAT / 4)      // 16 float4 per feature row
#define HALF   64              // edges per half-warp task
#define CHUNK  (2 * HALF)      // edges per warp
#define D      8               // prefetch depth (ring stages)
#define WPB    4               // warps per block
#define TPB    (WPB * 32)
#define MAX_E  1250000

__device__ int2 g_idx[MAX_E];

__global__ __launch_bounds__(256) void pack_idx_kernel(
    const void* __restrict__ ii_p, const void* __restrict__ jj_p, int E)
{
    int e = blockIdx.x * blockDim.x + threadIdx.x;
    if (e >= E) return;
    // dtype probe: LE int64 -> int32 word at odd position (E/2)|1 is a zero
    // high word; int32 -> sorted idx_i median ~N/2 != 0.
    int probe = reinterpret_cast<const int*>(ii_p)[(E / 2) | 1];
    int a, b;
    if (probe == 0) {
        a = (int)reinterpret_cast<const long long*>(ii_p)[e];
        b = (int)reinterpret_cast<const long long*>(jj_p)[e];
    } else {
        a = reinterpret_cast<const int*>(ii_p)[e];
        b = reinterpret_cast<const int*>(jj_p)[e];
    }
    g_idx[e] = make_int2(a, b);
}

__device__ __forceinline__ void red_add_f4(float* p, float4 v) {
    asm volatile("red.global.add.v4.f32 [%0], {%1,%2,%3,%4};"
                 :: "l"(p), "f"(v.x), "f"(v.y), "f"(v.z), "f"(v.w)
                 : "memory");
}

__device__ __forceinline__ void fma4(float4& a, float4 x, float4 w) {
    a.x = fmaf(x.x, w.x, a.x);
    a.y = fmaf(x.y, w.y, a.y);
    a.z = fmaf(x.z, w.z, a.z);
    a.w = fmaf(x.w, w.w, a.w);
}

__device__ __forceinline__ void flush(float* __restrict__ y, int seg, int fl,
                                      float4 acc, bool& first)
{
    float* dst = y + (size_t)seg * FEAT + fl * 4;
    if (first) { red_add_f4(dst, acc); first = false; }
    else       { *reinterpret_cast<float4*>(dst) = acc; }  // exclusive interior
}

__device__ __forceinline__ void cp16(void* smem_dst, const void* gmem_src) {
    unsigned       ds = (unsigned)__cvta_generic_to_shared(smem_dst);
    unsigned long long gs = (unsigned long long)__cvta_generic_to_global(gmem_src);
    asm volatile("cp.async.cg.shared.global [%0], [%1], 16;"
                 :: "r"(ds), "l"(gs) : "memory");
}

__global__ __launch_bounds__(TPB) void cfconv_kernel(
    const float4* __restrict__ X4, const float4* __restrict__ W4,
    float* __restrict__ y, int E)
{
    __shared__ float4 sW[WPB][D][32];
    __shared__ float4 sX[WPB][D][32];
    __shared__ int    sI[WPB][D][32];

    int tid  = threadIdx.x;
    int w    = tid >> 5;
    int lane = tid & 31;
    int half = lane >> 4;
    int fl   = lane & 15;

    int gwarp = blockIdx.x * WPB + w;
    long long base = (long long)gwarp * CHUNK;
    if (base >= E) return;
    long long s = base + (long long)half * HALF;
    if (s >= E) return;
    long long se = s + HALF; if (se > E) se = E;
    int cnt = (int)(se - s);

    const int2*   ip = g_idx + s;
    const float4* wp = W4 + (size_t)s * F4 + fl;

    int    prev;
    bool   first = true;               // first segment may start before s
    float4 acc   = make_float4(0.f, 0.f, 0.f, 0.f);

    if (cnt == HALF) {
        // -------- cp.async pipelined full-task path --------
        // prologue: fill all D stages (one commit group per stage)
        #pragma unroll
        for (int d = 0; d < D; ++d) {
            int2 id = ip[d];
            sI[w][d][lane] = id.x;
            cp16(&sW[w][d][lane], wp + (size_t)d * F4);
            cp16(&sX[w][d][lane], X4 + (size_t)id.y * F4 + fl);
            asm volatile("cp.async.commit_group;" ::: "memory");
        }
        prev = ip[0].x;                // L1 hit
        int2 idp = ip[D];              // idx for the first in-loop prefetch

        for (int k = 0; k < HALF; ++k) {
            // stage k's group is the 8th-newest -> all older complete
            asm volatile("cp.async.wait_group 7;" ::: "memory");
            int st = k & (D - 1);
            int    six = sI[w][st][lane];
            float4 wv  = sW[w][st][lane];
            float4 xv  = sX[w][st][lane];

            // prefetch edge k+D into the slot just consumed
            if (k + D < HALF) {
                sI[w][st][lane] = idp.x;
                cp16(&sW[w][st][lane], wp + (size_t)(k + D) * F4);
                cp16(&sX[w][st][lane], X4 + (size_t)idp.y * F4 + fl);
            }
            asm volatile("cp.async.commit_group;" ::: "memory");

            // idx for next iteration's prefetch (clamped; unused when guarded off)
            int ni = k + D + 1; if (ni > HALF - 1) ni = HALF - 1;
            idp = ip[ni];

            // consume edge k
            if (six != prev) {
                flush(y, prev, fl, acc, first);
                acc  = make_float4(0.f, 0.f, 0.f, 0.f);
                prev = six;
            }
            fma4(acc, xv, wv);
        }
    } else {
        // -------- scalar tail path (at most one partial task) --------
        int2   idc = ip[0];
        float4 wc  = __ldcs(wp);
        float4 xc  = X4[(size_t)idc.y * F4 + fl];
        prev = idc.x;
        for (int k = 1; k < cnt; ++k) {
            int2   idn = ip[k];
            float4 wn  = __ldcs(wp + (size_t)k * F4);
            float4 xn  = X4[(size_t)idn.y * F4 + fl];
            if (idc.x != prev) {
                flush(y, prev, fl, acc, first);
                acc  = make_float4(0.f, 0.f, 0.f, 0.f);
                prev = idc.x;
            }
            fma4(acc, xc, wc);
            idc = idn; wc = wn; xc = xn;
        }
        if (idc.x != prev) {
            flush(y, prev, fl, acc, first);
            acc  = make_float4(0.f, 0.f, 0.f, 0.f);
            prev = idc.x;
        }
        fma4(acc, xc, wc);
    }

    // final segment may extend into the next task -> atomic
    red_add_f4(y + (size_t)prev * FEAT + fl * 4, acc);
}

extern "C" void kernel_launch(void* const* d_in, const int* in_sizes, int n_in,
                              void* d_out, int out_size)
{
    const float* x   = (const float*)d_in[0];   // [N, 64]
    const float* Wij = (const float*)d_in[1];   // [E, 64]
    const void*  ii  = d_in[2];                 // [E] int64 or int32
    const void*  jj  = d_in[3];                 // [E] int64 or int32
    float*       y   = (float*)d_out;           // [N, 64]

    int E = in_sizes[1] / FEAT;

    cudaMemsetAsync(d_out, 0, (size_t)out_size * sizeof(float), 0);
    pack_idx_kernel<<<(E + 255) / 256, 256>>>(ii, jj, E);

    int nwarps  = (E + CHUNK - 1) / CHUNK;
    int nblocks = (nwarps + WPB - 1) / WPB;
    cfconv_kernel<<<nblocks, TPB>>>((const float4*)x, (const float4*)Wij, y, E);
}

// round 7
// speedup vs baseline: 1.1099x; 1.1099x over previous
#include <cuda_runtime.h>

// CFConv: y[i] = sum_{e: idx_i[e]==i} x[idx_j[e]] * Wij[e]
// x:[50000,64] f32, Wij:[E=1.25M,64] f32, idx_i sorted.
//
// R7: cp.async SMEM ring (R6) with D=6 for +33% occupancy (27.6KB/block ->
// 8 blocks/SM), pack kernel eliminated: main kernel reads idx_i/idx_j
// directly, templated int32/int64 via uniform device-side dtype probe.
// Half-warp float4 lanes; sorted-segment register accumulation; plain stores
// for interior segments; red.global.add.v4.f32 at task boundaries.

#define FEAT   64
#define F4     (FEAT / 4)      // 16 float4 per feature row
#define HALF   64              // edges per half-warp task
#define CHUNK  (2 * HALF)      // edges per warp
#define D      6               // prefetch depth (ring stages)
#define WPB    4               // warps per block
#define TPB    (WPB * 32)

__device__ __forceinline__ void red_add_f4(float* p, float4 v) {
    asm volatile("red.global.add.v4.f32 [%0], {%1,%2,%3,%4};"
                 :: "l"(p), "f"(v.x), "f"(v.y), "f"(v.z), "f"(v.w)
                 : "memory");
}

__device__ __forceinline__ void fma4(float4& a, float4 x, float4 w) {
    a.x = fmaf(x.x, w.x, a.x);
    a.y = fmaf(x.y, w.y, a.y);
    a.z = fmaf(x.z, w.z, a.z);
    a.w = fmaf(x.w, w.w, a.w);
}

__device__ __forceinline__ void flush(float* __restrict__ y, int seg, int fl,
                                      float4 acc, bool& first)
{
    float* dst = y + (size_t)seg * FEAT + fl * 4;
    if (first) { red_add_f4(dst, acc); first = false; }
    else       { *reinterpret_cast<float4*>(dst) = acc; }  // exclusive interior
}

__device__ __forceinline__ void cp16(void* smem_dst, const void* gmem_src) {
    unsigned           ds = (unsigned)__cvta_generic_to_shared(smem_dst);
    unsigned long long gs = (unsigned long long)__cvta_generic_to_global(gmem_src);
    asm volatile("cp.async.cg.shared.global [%0], [%1], 16;"
                 :: "r"(ds), "l"(gs) : "memory");
}

template <typename IdxT>
__device__ __forceinline__ void cfconv_body(
    const float4* __restrict__ X4, const float4* __restrict__ W4,
    const IdxT* __restrict__ idx_i, const IdxT* __restrict__ idx_j,
    float* __restrict__ y, int E,
    float4 (&sW)[WPB][D][32], float4 (&sX)[WPB][D][32], int (&sI)[WPB][D][32],
    int w, int lane, int half, int fl, long long s, int cnt)
{
    const float4* wp = W4 + (size_t)s * F4 + fl;

    int    prev;
    bool   first = true;               // first segment may start before s
    float4 acc   = make_float4(0.f, 0.f, 0.f, 0.f);

    if (cnt == HALF) {
        // -------- cp.async pipelined full-task path --------
        #pragma unroll
        for (int d = 0; d < D; ++d) {
            int ii = (int)idx_i[s + d];
            int jj = (int)idx_j[s + d];
            sI[w][d][lane] = ii;
            cp16(&sW[w][d][lane], wp + (size_t)d * F4);
            cp16(&sX[w][d][lane], X4 + (size_t)jj * F4 + fl);
            asm volatile("cp.async.commit_group;" ::: "memory");
        }
        prev = (int)idx_i[s];          // L1 hit
        int pi = (int)idx_i[s + D];    // idx for the first in-loop prefetch
        int pj = (int)idx_j[s + D];

        for (int k = 0; k < HALF; ++k) {
            asm volatile("cp.async.wait_group 5;" ::: "memory");
            int st = k % D;
            int    six = sI[w][st][lane];
            float4 wv  = sW[w][st][lane];
            float4 xv  = sX[w][st][lane];

            // prefetch edge k+D into the slot just consumed
            if (k + D < HALF) {
                sI[w][st][lane] = pi;
                cp16(&sW[w][st][lane], wp + (size_t)(k + D) * F4);
                cp16(&sX[w][st][lane], X4 + (size_t)pj * F4 + fl);
            }
            asm volatile("cp.async.commit_group;" ::: "memory");

            // idx for next iteration's prefetch (clamped; L1 broadcast hits)
            int ni = k + D + 1; if (ni > HALF - 1) ni = HALF - 1;
            pi = (int)idx_i[s + ni];
            pj = (int)idx_j[s + ni];

            // consume edge k
            if (six != prev) {
                flush(y, prev, fl, acc, first);
                acc  = make_float4(0.f, 0.f, 0.f, 0.f);
                prev = six;
            }
            fma4(acc, xv, wv);
        }
    } else {
        // -------- scalar tail path (at most one partial task) --------
        int    ic = (int)idx_i[s];
        int    jc = (int)idx_j[s];
        float4 wc = __ldcs(wp);
        float4 xc = X4[(size_t)jc * F4 + fl];
        prev = ic;
        for (int k = 1; k < cnt; ++k) {
            int    in_ = (int)idx_i[s + k];
            int    jn  = (int)idx_j[s + k];
            float4 wn  = __ldcs(wp + (size_t)k * F4);
            float4 xn  = X4[(size_t)jn * F4 + fl];
            if (ic != prev) {
                flush(y, prev, fl, acc, first);
                acc  = make_float4(0.f, 0.f, 0.f, 0.f);
                prev = ic;
            }
            fma4(acc, xc, wc);
            ic = in_; wc = wn; xc = xn;
        }
        if (ic != prev) {
            flush(y, prev, fl, acc, first);
            acc  = make_float4(0.f, 0.f, 0.f, 0.f);
            prev = ic;
        }
        fma4(acc, xc, wc);
    }

    // final segment may extend into the next task -> atomic
    red_add_f4(y + (size_t)prev * FEAT + fl * 4, acc);
}

__global__ __launch_bounds__(TPB) void cfconv_kernel(
    const float4* __restrict__ X4, const float4* __restrict__ W4,
    const void* __restrict__ ii_p, const void* __restrict__ jj_p,
    float* __restrict__ y, int E)
{
    __shared__ float4 sW[WPB][D][32];
    __shared__ float4 sX[WPB][D][32];
    __shared__ int    sI[WPB][D][32];

    int tid  = threadIdx.x;
    int w    = tid >> 5;
    int lane = tid & 31;
    int half = lane >> 4;
    int fl   = lane & 15;

    int gwarp = blockIdx.x * WPB + w;
    long long base = (long long)gwarp * CHUNK;
    if (base >= E) return;
    long long s = base + (long long)half * HALF;
    if (s >= E) return;
    long long se = s + HALF; if (se > E) se = E;
    int cnt = (int)(se - s);

    // dtype probe (uniform): LE int64 -> int32 word at odd position (E/2)|1 is
    // a zero high word; int32 -> sorted idx_i median ~N/2 != 0.
    int probe = reinterpret_cast<const int*>(ii_p)[(E / 2) | 1];
    if (probe == 0) {
        cfconv_body<long long>(X4, W4,
                               reinterpret_cast<const long long*>(ii_p),
                               reinterpret_cast<const long long*>(jj_p),
                               y, E, sW, sX, sI, w, lane, half, fl, s, cnt);
    } else {
        cfconv_body<int>(X4, W4,
                         reinterpret_cast<const int*>(ii_p),
                         reinterpret_cast<const int*>(jj_p),
                         y, E, sW, sX, sI, w, lane, half, fl, s, cnt);
    }
}

extern "C" void kernel_launch(void* const* d_in, const int* in_sizes, int n_in,
                              void* d_out, int out_size)
{
    const float* x   = (const float*)d_in[0];   // [N, 64]
    const float* Wij = (const float*)d_in[1];   // [E, 64]
    const void*  ii  = d_in[2];                 // [E] int64 or int32
    const void*  jj  = d_in[3];                 // [E] int64 or int32
    float*       y   = (float*)d_out;           // [N, 64]

    int E = in_sizes[1] / FEAT;

    // zero output (memset node — graph-capturable)
    cudaMemsetAsync(d_out, 0, (size_t)out_size * sizeof(float), 0);

    int nwarps  = (E + CHUNK - 1) / CHUNK;
    int nblocks = (nwarps + WPB - 1) / WPB;
    cfconv_kernel<<<nblocks, TPB>>>((const float4*)x, (const float4*)Wij,
                                    ii, jj, y, E);
}

// round 8
// speedup vs baseline: 1.1135x; 1.0032x over previous
#include <cuda_runtime.h>

// CFConv: y[i] = sum_{e: idx_i[e]==i} x[idx_j[e]] * Wij[e]
// x:[50000,64] f32, Wij:[E=1.25M,64] f32, idx_i sorted.
//
// R8: cp.async SMEM ring (W stream + x gather, D=6) with the sI index ring
// removed (consume idx via depth-1 register + prefetch.global.L1 at distance
// D), and WPB=2/TPB=64 so smem drops to 12KB/block -> 19 blocks/SM (~38
// warps). Half-warp float4 lanes; sorted-segment register accumulation;
// plain stores for interior segments; red.global.add.v4.f32 at boundaries.

#define FEAT   64
#define F4     (FEAT / 4)      // 16 float4 per feature row
#define HALF   64              // edges per half-warp task
#define CHUNK  (2 * HALF)      // edges per warp
#define D      6               // prefetch depth (ring stages)
#define WPB    2               // warps per block
#define TPB    (WPB * 32)

__device__ __forceinline__ void red_add_f4(float* p, float4 v) {
    asm volatile("red.global.add.v4.f32 [%0], {%1,%2,%3,%4};"
                 :: "l"(p), "f"(v.x), "f"(v.y), "f"(v.z), "f"(v.w)
                 : "memory");
}

__device__ __forceinline__ void fma4(float4& a, float4 x, float4 w) {
    a.x = fmaf(x.x, w.x, a.x);
    a.y = fmaf(x.y, w.y, a.y);
    a.z = fmaf(x.z, w.z, a.z);
    a.w = fmaf(x.w, w.w, a.w);
}

__device__ __forceinline__ void flush(float* __restrict__ y, int seg, int fl,
                                      float4 acc, bool& first)
{
    float* dst = y + (size_t)seg * FEAT + fl * 4;
    if (first) { red_add_f4(dst, acc); first = false; }
    else       { *reinterpret_cast<float4*>(dst) = acc; }  // exclusive interior
}

__device__ __forceinline__ void cp16(void* smem_dst, const void* gmem_src) {
    unsigned           ds = (unsigned)__cvta_generic_to_shared(smem_dst);
    unsigned long long gs = (unsigned long long)__cvta_generic_to_global(gmem_src);
    asm volatile("cp.async.cg.shared.global [%0], [%1], 16;"
                 :: "r"(ds), "l"(gs) : "memory");
}

template <typename T>
__device__ __forceinline__ void pf_l1(const T* p) {
    asm volatile("prefetch.global.L1 [%0];" :: "l"(p));
}

template <typename IdxT>
__device__ __forceinline__ void cfconv_body(
    const float4* __restrict__ X4, const float4* __restrict__ W4,
    const IdxT* __restrict__ idx_i, const IdxT* __restrict__ idx_j,
    float* __restrict__ y,
    float4 (&sW)[WPB][D][32], float4 (&sX)[WPB][D][32],
    int w, int lane, int fl, long long s, int cnt)
{
    const float4* wp = W4 + (size_t)s * F4 + fl;

    int    prev;
    bool   first = true;               // first segment may start before s
    float4 acc   = make_float4(0.f, 0.f, 0.f, 0.f);

    if (cnt == HALF) {
        // -------- cp.async pipelined full-task path --------
        #pragma unroll
        for (int d = 0; d < D; ++d) {
            int jj = (int)idx_j[s + d];
            cp16(&sW[w][d][lane], wp + (size_t)d * F4);
            cp16(&sX[w][d][lane], X4 + (size_t)jj * F4 + fl);
            asm volatile("cp.async.commit_group;" ::: "memory");
        }
        int ci = (int)idx_i[s];        // consume idx, depth-1 staged
        prev   = ci;
        int pj = (int)idx_j[s + D];    // gather idx for first in-loop prefetch

        for (int k = 0; k < HALF; ++k) {
            asm volatile("cp.async.wait_group %0;" :: "n"(D - 1) : "memory");
            int st = k % D;
            float4 wv = sW[w][st][lane];
            float4 xv = sX[w][st][lane];

            // prefetch edge k+D into the slot just consumed
            if (k + D < HALF) {
                cp16(&sW[w][st][lane], wp + (size_t)(k + D) * F4);
                cp16(&sX[w][st][lane], X4 + (size_t)pj * F4 + fl);
                pf_l1(idx_i + s + k + D);          // keep idx_i line L1-hot
            }
            asm volatile("cp.async.commit_group;" ::: "memory");

            // stage next-iteration indices (clamped; L1 hits)
            int nc = k + 1;     if (nc > HALF - 1) nc = HALF - 1;
            int np = k + D + 1; if (np > HALF - 1) np = HALF - 1;
            int ci_n = (int)idx_i[s + nc];
            pj       = (int)idx_j[s + np];

            // consume edge k
            if (ci != prev) {
                flush(y, prev, fl, acc, first);
                acc  = make_float4(0.f, 0.f, 0.f, 0.f);
                prev = ci;
            }
            fma4(acc, xv, wv);
            ci = ci_n;
        }
    } else {
        // -------- scalar tail path (at most one partial task) --------
        int    ic = (int)idx_i[s];
        int    jc = (int)idx_j[s];
        float4 wc = __ldcs(wp);
        float4 xc = X4[(size_t)jc * F4 + fl];
        prev = ic;
        for (int k = 1; k < cnt; ++k) {
            int    in_ = (int)idx_i[s + k];
            int    jn  = (int)idx_j[s + k];
            float4 wn  = __ldcs(wp + (size_t)k * F4);
            float4 xn  = X4[(size_t)jn * F4 + fl];
            if (ic != prev) {
                flush(y, prev, fl, acc, first);
                acc  = make_float4(0.f, 0.f, 0.f, 0.f);
                prev = ic;
            }
            fma4(acc, xc, wc);
            ic = in_; wc = wn; xc = xn;
        }
        if (ic != prev) {
            flush(y, prev, fl, acc, first);
            acc  = make_float4(0.f, 0.f, 0.f, 0.f);
            prev = ic;
        }
        fma4(acc, xc, wc);
    }

    // final segment may extend into the next task -> atomic
    red_add_f4(y + (size_t)prev * FEAT + fl * 4, acc);
}

__global__ __launch_bounds__(TPB) void cfconv_kernel(
    const float4* __restrict__ X4, const float4* __restrict__ W4,
    const void* __restrict__ ii_p, const void* __restrict__ jj_p,
    float* __restrict__ y, int E)
{
    __shared__ float4 sW[WPB][D][32];
    __shared__ float4 sX[WPB][D][32];

    int tid  = threadIdx.x;
    int w    = tid >> 5;
    int lane = tid & 31;
    int half = lane >> 4;
    int fl   = lane & 15;

    int gwarp = blockIdx.x * WPB + w;
    long long base = (long long)gwarp * CHUNK;
    if (base >= E) return;
    long long s = base + (long long)half * HALF;
    if (s >= E) return;
    long long se = s + HALF; if (se > E) se = E;
    int cnt = (int)(se - s);

    // dtype probe (uniform): LE int64 -> int32 word at odd position (E/2)|1 is
    // a zero high word; int32 -> sorted idx_i median ~N/2 != 0.
    int probe = reinterpret_cast<const int*>(ii_p)[(E / 2) | 1];
    if (probe == 0) {
        cfconv_body<long long>(X4, W4,
                               reinterpret_cast<const long long*>(ii_p),
                               reinterpret_cast<const long long*>(jj_p),
                               y, sW, sX, w, lane, fl, s, cnt);
    } else {
        cfconv_body<int>(X4, W4,
                         reinterpret_cast<const int*>(ii_p),
                         reinterpret_cast<const int*>(jj_p),
                         y, sW, sX, w, lane, fl, s, cnt);
    }
}

extern "C" void kernel_launch(void* const* d_in, const int* in_sizes, int n_in,
                              void* d_out, int out_size)
{
    const float* x   = (const float*)d_in[0];   // [N, 64]
    const float* Wij = (const float*)d_in[1];   // [E, 64]
    const void*  ii  = d_in[2];                 // [E] int64 or int32
    const void*  jj  = d_in[3];                 // [E] int64 or int32
    float*       y   = (float*)d_out;           // [N, 64]

    int E = in_sizes[1] / FEAT;

    // zero output (memset node — graph-capturable)
    cudaMemsetAsync(d_out, 0, (size_t)out_size * sizeof(float), 0);

    int nwarps  = (E + CHUNK - 1) / CHUNK;
    int nblocks = (nwarps + WPB - 1) / WPB;
    cfconv_kernel<<<nblocks, TPB>>>((const float4*)x, (const float4*)Wij,
                                    ii, jj, y, E);
}